// round 9
// baseline (speedup 1.0000x reference)
#include <cuda_runtime.h>

// LieTransport bilinear backward warp — 2 pixel-pairs per block, deep MLP.
// h_prev: [B=4, C=64, H=128, W=128, R=16] fp32 (64B per (b,c,y,x) vector)
//
// Per block: 4 consecutive x pixels (two pairs). All 16 span loads issued
// before any compute so pair B's loads hide pair A's compute (and the next
// block's loads hide this block's tail). Per pair: 128B span loads (both
// x-taps contiguous), per-lane y-blend, float4 shfl_xor(4) exchange,
// x-blend, folded full-warp 128B-line .cs stores.

#define Hd 128
#define Wd 128
#define Cd 64
#define HWd (Hd * Wd)

struct Coords {
    int   tbase, bbase, obase;   // float4 indices (channel j=0 plane)
    float wy, cs, co;
};

__device__ __forceinline__ Coords make_coords(
    const float* __restrict__ flow, float d,
    int b, int x, int y, int e, int q, int h, int plane0)
{
    const int   fb = ((b * 2) * Hd + y) * Wd + x;
    const float fx = flow[fb];
    const float fy = flow[fb + HWd];

    const float gx = fmaf((float)x, 2.0f / (Wd - 1), -1.0f) - fx * d;
    const float gy = fmaf((float)y, 2.0f / (Hd - 1), -1.0f) - fy * d;

    const float ix = fminf(fmaxf(((gx + 1.0f) * (float)Wd - 1.0f) * 0.5f, 0.0f), (float)(Wd - 1));
    const float iy = fminf(fmaxf(((gy + 1.0f) * (float)Hd - 1.0f) * 0.5f, 0.0f), (float)(Hd - 1));

    const float x0f = floorf(ix);
    const float y0f = floorf(iy);
    const float wx  = ix - x0f;

    const int x0 = (int)x0f;
    const int y0 = (int)y0f;
    const int y1 = min(y0 + 1, Hd - 1);
    const int xs = min(x0, Wd - 2);

    const bool edge = (x0 == Wd - 1);
    const float c0 = edge ? 0.0f : (1.0f - wx);
    const float c1 = edge ? 1.0f : wx;

    Coords c;
    c.wy    = iy - y0f;
    c.cs    = h ? c1 : c0;
    c.co    = h ? c0 : c1;
    c.tbase = (plane0 + y0 * Wd + xs) * 4 + e;
    c.bbase = (plane0 + y1 * Wd + xs) * 4 + e;
    c.obase = (plane0 + y  * Wd + x ) * 4 + q;
    return c;
}

__global__ __launch_bounds__(256) void lie_transport_kernel(
    const float4* __restrict__ h4,
    const float*  __restrict__ flow,
    const float*  __restrict__ dt,
    float4*       __restrict__ out4)
{
    const int tid  = threadIdx.x;
    const int lane = tid & 31;
    const int w    = tid >> 5;        // warp 0..7
    const int e    = lane & 7;        // position in 128B span
    const int h    = e >> 2;          // span half (x-tap 0 or 1)
    const int q    = e & 3;           // float4 quarter of R=16
    const int it   = lane >> 3;       // item 0..3
    const int px   = it & 1;          // pixel of pair
    const int k    = it >> 1;         // channel sub-slot 0..1

    const int bid = blockIdx.x;
    const int qx  = bid & (Wd / 4 - 1);          // 4-pixel group in row
    const int y   = (bid >> 5) & (Hd - 1);
    const int b   = bid >> 12;

    const float d = dt[b];
    const int plane0 = (b * Cd + (k * 8 + w)) * HWd;  // channel for j=0
    const int jstep  = 16 * HWd * 4;                  // channel += 16 / round

    const int xA = 4 * qx + px;        // pair A pixel
    const int xB = xA + 2;             // pair B pixel

    const Coords cA = make_coords(flow, d, b, xA, y, e, q, h, plane0);
    const Coords cB = make_coords(flow, d, b, xB, y, e, q, h, plane0);

    // ---- issue ALL 16 span loads up front (MLP = 16) ----
    float4 tA[4], bA[4], tB[4], bB[4];
#pragma unroll
    for (int j = 0; j < 4; ++j) {
        tA[j] = __ldg(h4 + cA.tbase + j * jstep);
        bA[j] = __ldg(h4 + cA.bbase + j * jstep);
    }
#pragma unroll
    for (int j = 0; j < 4; ++j) {
        tB[j] = __ldg(h4 + cB.tbase + j * jstep);
        bB[j] = __ldg(h4 + cB.bbase + j * jstep);
    }

    // ---- compute + store, pair A then pair B ----
#pragma unroll
    for (int p = 0; p < 2; ++p) {
        const Coords& c  = p ? cB : cA;
        const float4* t  = p ? tB : tA;
        const float4* bt = p ? bB : bA;

        float4 rprev;
#pragma unroll
        for (int j = 0; j < 4; ++j) {
            float4 m;
            m.x = fmaf(c.wy, bt[j].x - t[j].x, t[j].x);
            m.y = fmaf(c.wy, bt[j].y - t[j].y, t[j].y);
            m.z = fmaf(c.wy, bt[j].z - t[j].z, t[j].z);
            m.w = fmaf(c.wy, bt[j].w - t[j].w, t[j].w);

            float4 mo;
            mo.x = __shfl_xor_sync(0xffffffffu, m.x, 4);
            mo.y = __shfl_xor_sync(0xffffffffu, m.y, 4);
            mo.z = __shfl_xor_sync(0xffffffffu, m.z, 4);
            mo.w = __shfl_xor_sync(0xffffffffu, m.w, 4);

            float4 r;
            r.x = fmaf(c.co, mo.x, c.cs * m.x);
            r.y = fmaf(c.co, mo.y, c.cs * m.y);
            r.z = fmaf(c.co, mo.z, c.cs * m.z);
            r.w = fmaf(c.co, mo.w, c.cs * m.w);

            if ((j & 1) == 0) {
                rprev = r;
            } else {
                const float4 rv = h ? r : rprev;
                __stcs(out4 + c.obase + (j - 1 + h) * jstep, rv);
            }
        }
    }
}

extern "C" void kernel_launch(void* const* d_in, const int* in_sizes, int n_in,
                              void* d_out, int out_size)
{
    const float* h_prev = (const float*)d_in[0];
    const float* flow   = (const float*)d_in[1];
    const float* dt     = (const float*)d_in[2];
    float* out          = (float*)d_out;

    const int B = 4;
    dim3 grid(B * Hd * (Wd / 4));   // 16384 blocks, two pixel pairs each
    dim3 block(256);

    lie_transport_kernel<<<grid, block>>>(
        (const float4*)h_prev, flow, dt, (float4*)out);
}

// round 10
// speedup vs baseline: 1.0829x; 1.0829x over previous
#include <cuda_runtime.h>
#include <cuda_fp16.h>

// LieTransport bilinear backward warp — span loads + folded stores +
// fp16-packed butterfly exchange (halves SHFL wavefronts).
// h_prev: [B=4, C=64, H=128, W=128, R=16] fp32 (64B per (b,c,y,x) vector)
//
// Taps (y,x0),(y,x0+1) are contiguous 128B -> one 8-lane span load per
// (row,pixel,channel). y-blend per lane. Exchange of the partner column is
// done as 2x half2 shfl_xor(4) (partner term weighted by co<=1, fp16
// rounding adds ~1e-4 norm error, tolerance 1e-3). Own term stays fp32.
// Stores folded to full-warp 128B-line .cs stores (no divergence).

#define Hd 128
#define Wd 128
#define Cd 64
#define HWd (Hd * Wd)

__global__ __launch_bounds__(256) void lie_transport_kernel(
    const float4* __restrict__ h4,
    const float*  __restrict__ flow,
    const float*  __restrict__ dt,
    float4*       __restrict__ out4)
{
    const int tid  = threadIdx.x;
    const int lane = tid & 31;
    const int w    = tid >> 5;        // warp 0..7
    const int e    = lane & 7;        // position in 128B span
    const int h    = e >> 2;          // span half (x-tap 0 or 1)
    const int q    = e & 3;           // float4 quarter of R=16
    const int it   = lane >> 3;       // item 0..3
    const int px   = it & 1;          // pixel of pair
    const int k    = it >> 1;         // channel sub-slot 0..1

    const int pp = blockIdx.x;
    const int xp = pp & (Wd / 2 - 1);
    const int y  = (pp >> 6) & (Hd - 1);
    const int b  = pp >> 13;
    const int x  = 2 * xp + px;

    // ---- sampling coordinates for this thread's pixel ----
    const float d  = dt[b];
    const int   fb = ((b * 2) * Hd + y) * Wd + x;
    const float fx = flow[fb];
    const float fy = flow[fb + HWd];

    const float gx = fmaf((float)x, 2.0f / (Wd - 1), -1.0f) - fx * d;
    const float gy = fmaf((float)y, 2.0f / (Hd - 1), -1.0f) - fy * d;

    const float ix = fminf(fmaxf(((gx + 1.0f) * (float)Wd - 1.0f) * 0.5f, 0.0f), (float)(Wd - 1));
    const float iy = fminf(fmaxf(((gy + 1.0f) * (float)Hd - 1.0f) * 0.5f, 0.0f), (float)(Hd - 1));

    const float x0f = floorf(ix);
    const float y0f = floorf(iy);
    const float wx  = ix - x0f;
    const float wy  = iy - y0f;

    const int x0 = (int)x0f;
    const int y0 = (int)y0f;
    const int y1 = min(y0 + 1, Hd - 1);
    const int xs = min(x0, Wd - 2);          // span start (always in-bounds)

    // x-blend weights per span half; clamp case x0==W-1 -> weights (0,1)
    const bool edge = (x0 == Wd - 1);
    const float c0 = edge ? 0.0f : (1.0f - wx);
    const float c1 = edge ? 1.0f : wx;
    const float cs = h ? c1 : c0;            // my half's weight
    const float co = h ? c0 : c1;            // other half's weight

    // ---- issue all 8 span loads up front (MLP = 8) ----
    const int plane0 = (b * Cd + (k * 8 + w)) * HWd;   // channel for j=0
    const int tbase  = (plane0 + y0 * Wd + xs) * 4 + e;
    const int bbase  = (plane0 + y1 * Wd + xs) * 4 + e;
    const int obase  = (plane0 + y  * Wd + x ) * 4 + q;
    const int jstep  = 16 * HWd * 4;                    // channel += 16 per round

    float4 t[4], bt[4];
#pragma unroll
    for (int j = 0; j < 4; ++j) {
        t[j]  = __ldg(h4 + tbase + j * jstep);
        bt[j] = __ldg(h4 + bbase + j * jstep);
    }

    float4 rprev;
#pragma unroll
    for (int j = 0; j < 4; ++j) {
        float4 m;   // this half-column interpolated in y (fp32)
        m.x = fmaf(wy, bt[j].x - t[j].x, t[j].x);
        m.y = fmaf(wy, bt[j].y - t[j].y, t[j].y);
        m.z = fmaf(wy, bt[j].z - t[j].z, t[j].z);
        m.w = fmaf(wy, bt[j].w - t[j].w, t[j].w);

        // pack to half2 and exchange with the other span half (2 SHFLs)
        const __half2 p01 = __floats2half2_rn(m.x, m.y);
        const __half2 p23 = __floats2half2_rn(m.z, m.w);
        const unsigned u01 = __shfl_xor_sync(0xffffffffu,
                                             *reinterpret_cast<const unsigned*>(&p01), 4);
        const unsigned u23 = __shfl_xor_sync(0xffffffffu,
                                             *reinterpret_cast<const unsigned*>(&p23), 4);
        const float2 mo01 = __half22float2(*reinterpret_cast<const __half2*>(&u01));
        const float2 mo23 = __half22float2(*reinterpret_cast<const __half2*>(&u23));

        float4 r;   // own term fp32, partner term fp16-rounded (co<=1)
        r.x = fmaf(co, mo01.x, cs * m.x);
        r.y = fmaf(co, mo01.y, cs * m.y);
        r.z = fmaf(co, mo23.x, cs * m.z);
        r.w = fmaf(co, mo23.y, cs * m.w);

        if ((j & 1) == 0) {
            rprev = r;
        } else {
            // folded store: h==0 lanes write round j-1's channel,
            // h==1 lanes write round j's channel. 4 full 128B lines/instr.
            const float4 rv = h ? r : rprev;
            __stcs(out4 + obase + (j - 1 + h) * jstep, rv);
        }
    }
}

extern "C" void kernel_launch(void* const* d_in, const int* in_sizes, int n_in,
                              void* d_out, int out_size)
{
    const float* h_prev = (const float*)d_in[0];
    const float* flow   = (const float*)d_in[1];
    const float* dt     = (const float*)d_in[2];
    float* out          = (float*)d_out;

    const int B = 4;
    dim3 grid(B * Hd * (Wd / 2));   // 32768 blocks, one per pixel pair
    dim3 block(256);

    lie_transport_kernel<<<grid, block>>>(
        (const float4*)h_prev, flow, dt, (float4*)out);
}